// round 4
// baseline (speedup 1.0000x reference)
#include <cuda_runtime.h>
#include <math.h>

#define NB 32
#define NL 128
#define NH 512
#define NG 2048
#define NV 32000
#define NE 128
#define NTOK 4096
#define NVT 250

// ------------------ scratch ------------------
__device__ float g_x0[NTOK * NE];
__device__ float g_gx[2u * NTOK * NG];          // [dir][m][g], m = b*128+t
__device__ float g_bufA[NTOK * 1024];
__device__ float g_bufB[NTOK * 1024];
__device__ float g_hid[NTOK * 128];
__device__ float g_h[2 * NB * NH];
__device__ float g_pmax[(size_t)NTOK * NVT];
__device__ float g_psum[(size_t)NTOK * NVT];
__device__ int   g_parg[(size_t)NTOK * NVT];
__device__ float g_nllw[NTOK];
__device__ float g_wtok[NTOK];
__device__ unsigned int g_barcnt;

// ------------------ helpers ------------------
__device__ __forceinline__ float sigf(float x) {
    return 1.0f / (1.0f + __expf(-x));
}
__device__ __forceinline__ float tanhf_fast(float x) {
    float e = __expf(-2.0f * fabsf(x));
    float r = (1.0f - e) / (1.0f + e);
    return copysignf(r, x);
}

__device__ __forceinline__ void gridbar() {
    __threadfence();
    __syncthreads();
    if (threadIdx.x == 0) {
        unsigned int t = atomicAdd(&g_barcnt, 1u);
        unsigned int need = ((t >> 7) + 1u) << 7;   // /128, +1, *128
        while (*((volatile unsigned int*)&g_barcnt) < need) {
            __nanosleep(32);
        }
    }
    __syncthreads();
}

// ------------------ embedding ------------------
__global__ __launch_bounds__(256) void k_embed(const int* __restrict__ w,
                                               const float* __restrict__ emb) {
    int i = blockIdx.x * 256 + threadIdx.x;      // 0 .. NTOK*NE-1
    g_x0[i] = emb[(size_t)w[i >> 7] * NE + (i & 127)];
}

// ------------------ zero h + barrier counter ------------------
__global__ __launch_bounds__(256) void k_zero() {
    int i = blockIdx.x * 256 + threadIdx.x;
    if (i < 2 * NB * NH) g_h[i] = 0.0f;
    if (i == 0) g_barcnt = 0u;
}

// ------------------ SGEMM v2: C[m][n] = act(sum_k A[m][k]*W[n][k] + bias[n]) ------------------
// 128x128 tile, BK=8, 256 threads, 8x8 microtile. blockIdx.z = dir.
__global__ __launch_bounds__(256) void k_gemm(const float* __restrict__ A,
                                              const float* __restrict__ W,
                                              const float* __restrict__ bias,
                                              float* __restrict__ C,
                                              int K, int N,
                                              long long wStr, long long bStr,
                                              long long cStr, int relu) {
    int d = blockIdx.z;
    W += (size_t)d * wStr;
    bias += (size_t)d * bStr;
    C += (size_t)d * cStr;

    __shared__ float As[8][128];
    __shared__ float Bs[8][128];

    int tid = threadIdx.x;
    int m0 = blockIdx.y << 7, n0 = blockIdx.x << 7;
    int lr = tid >> 1, lkq = (tid & 1) << 2;
    int tx = tid & 15, ty = tid >> 4;

    const float* Ap = A + (size_t)(m0 + lr) * K + lkq;
    const float* Wp = W + (size_t)(n0 + lr) * K + lkq;

    float acc[8][8];
#pragma unroll
    for (int i = 0; i < 8; i++)
#pragma unroll
        for (int j = 0; j < 8; j++) acc[i][j] = 0.0f;

    for (int k0 = 0; k0 < K; k0 += 8) {
        float4 av = *(const float4*)(Ap + k0);
        float4 wv = *(const float4*)(Wp + k0);
        __syncthreads();
        As[lkq + 0][lr] = av.x; As[lkq + 1][lr] = av.y;
        As[lkq + 2][lr] = av.z; As[lkq + 3][lr] = av.w;
        Bs[lkq + 0][lr] = wv.x; Bs[lkq + 1][lr] = wv.y;
        Bs[lkq + 2][lr] = wv.z; Bs[lkq + 3][lr] = wv.w;
        __syncthreads();
#pragma unroll
        for (int k = 0; k < 8; k++) {
            float4 a0 = *(const float4*)&As[k][ty << 3];
            float4 a1 = *(const float4*)&As[k][(ty << 3) + 4];
            float4 b0 = *(const float4*)&Bs[k][tx << 3];
            float4 b1 = *(const float4*)&Bs[k][(tx << 3) + 4];
            float av8[8] = {a0.x, a0.y, a0.z, a0.w, a1.x, a1.y, a1.z, a1.w};
            float bv8[8] = {b0.x, b0.y, b0.z, b0.w, b1.x, b1.y, b1.z, b1.w};
#pragma unroll
            for (int i = 0; i < 8; i++)
#pragma unroll
                for (int j = 0; j < 8; j++) acc[i][j] += av8[i] * bv8[j];
        }
    }

#pragma unroll
    for (int i = 0; i < 8; i++) {
        int m = m0 + (ty << 3) + i;
        float* crow = C + (size_t)m * N + n0 + (tx << 3);
#pragma unroll
        for (int j = 0; j < 8; j++) {
            float v = acc[i][j] + bias[n0 + (tx << 3) + j];
            if (relu) v = fmaxf(v, 0.0f);
            acc[i][j] = v;
        }
        float4 o0 = {acc[i][0], acc[i][1], acc[i][2], acc[i][3]};
        float4 o1 = {acc[i][4], acc[i][5], acc[i][6], acc[i][7]};
        *(float4*)crow = o0;
        *(float4*)(crow + 4) = o1;
    }
}

// ------------------ persistent BiLSTM layer scan v2 ------------------
// 128 blocks x 128 threads. Block = (dir, 8-wide j-slice, all 4 gates).
// Whh slice resident in smem; c/h in registers; 1 grid barrier per step.
__global__ __launch_bounds__(128) void k_scan(const float* __restrict__ gx,
                                              const float* __restrict__ whh,
                                              const float* __restrict__ mask,
                                              float* __restrict__ out) {
    extern __shared__ float sm[];
    float* Ws = sm;                     // [32][512]  rows: (g*8+q) -> gate g, j0+q
    float* Hs = sm + 32 * 512;          // [32][516]  (b-major, padded)
    float* Gs = sm + 32 * 512 + 32 * 516; // [4][8][32]

    int tid = threadIdx.x;
    int bid = blockIdx.x;
    int d = bid >> 6;
    int jt = bid & 63;
    int j0 = jt << 3;
    const float* whhd = whh + (size_t)d * NG * NH;

    // preload weight slice into smem (once per layer)
#pragma unroll
    for (int it = 0; it < 32; it++) {
        int idx = it * 512 + (tid << 2);
        int ridx = idx >> 9, k = idx & 511;
        int grow = ((ridx >> 3) << 9) + j0 + (ridx & 7);
        float4 v = __ldg((const float4*)(whhd + (size_t)grow * NH + k));
        *(float4*)&Ws[ridx * 512 + k] = v;
    }

    int w = tid >> 5;        // warp id = gate id
    int lane = tid & 31;     // batch id

    int cb = tid & 31;       // combine role: batch
    int cq = tid >> 5;       // combine role: handles q = cq*2, cq*2+1

    float hreg[2] = {0.0f, 0.0f};
    float creg[2] = {0.0f, 0.0f};

    const float* ghd = g_h + (size_t)d * NB * NH;
    float* ghw = g_h + (size_t)d * NB * NH;

    __syncthreads();

    for (int s = 0; s < NL; s++) {
        int t = d ? (NL - 1 - s) : s;

        // ---- stage h[d] into smem (coalesced) ----
#pragma unroll
        for (int it = 0; it < 32; it++) {
            int idx = it * 512 + (tid << 2);
            int b = idx >> 9, k = idx & 511;
            float4 v = __ldcg((const float4*)(ghd + b * 512 + k));
            *(float4*)&Hs[b * 516 + k] = v;
        }
        __syncthreads();

        // ---- recurrent dot: acc[q] for gate w, rows j0+q, batch=lane ----
        float acc[8];
#pragma unroll
        for (int q = 0; q < 8; q++) acc[q] = 0.0f;
        const float* wbase = &Ws[(w << 3) * 512];
        const float* hrow = &Hs[lane * 516];
        for (int k = 0; k < 512; k += 4) {
            float4 hv = *(const float4*)&hrow[k];
#pragma unroll
            for (int q = 0; q < 8; q++) {
                float4 wv = *(const float4*)&wbase[q * 512 + k];
                acc[q] += wv.x * hv.x + wv.y * hv.y + wv.z * hv.z + wv.w * hv.w;
            }
        }

        // ---- add input-gate preactivation, exchange via smem ----
        const float* gp = gx + ((size_t)d * NTOK + (size_t)lane * NL + t) * NG + (w << 9) + j0;
        float4 g0 = __ldg((const float4*)gp);
        float4 g1 = __ldg((const float4*)(gp + 4));
        Gs[((w << 3) + 0) * 32 + lane] = acc[0] + g0.x;
        Gs[((w << 3) + 1) * 32 + lane] = acc[1] + g0.y;
        Gs[((w << 3) + 2) * 32 + lane] = acc[2] + g0.z;
        Gs[((w << 3) + 3) * 32 + lane] = acc[3] + g0.w;
        Gs[((w << 3) + 4) * 32 + lane] = acc[4] + g1.x;
        Gs[((w << 3) + 5) * 32 + lane] = acc[5] + g1.y;
        Gs[((w << 3) + 6) * 32 + lane] = acc[6] + g1.z;
        Gs[((w << 3) + 7) * 32 + lane] = acc[7] + g1.w;
        __syncthreads();

        // ---- cell update (c,h live in registers, block-private j slice) ----
        float mt = mask[cb * NL + t];
#pragma unroll
        for (int r = 0; r < 2; r++) {
            int q = (cq << 1) + r;
            float gi = Gs[(0 * 8 + q) * 32 + cb];
            float gf = Gs[(1 * 8 + q) * 32 + cb];
            float gg = Gs[(2 * 8 + q) * 32 + cb];
            float go = Gs[(3 * 8 + q) * 32 + cb];
            float cn = sigf(gf) * creg[r] + sigf(gi) * tanhf_fast(gg);
            float hn = sigf(go) * tanhf_fast(cn);
            float hh = hreg[r] + (hn - hreg[r]) * mt;
            creg[r] = creg[r] + (cn - creg[r]) * mt;
            hreg[r] = hh;
            int j = j0 + q;
            ghw[cb * NH + j] = hh;
            out[((size_t)cb * NL + t) * 1024 + (d << 9) + j] = hh;
        }
        gridbar();
    }
}

// ------------------ decoder2: logits tile + online softmax partials ------------------
__global__ __launch_bounds__(256) void k_dec2(const float* __restrict__ w2,
                                              const float* __restrict__ b2) {
    int vt = blockIdx.x;   // 0..249
    int mt = blockIdx.y;   // 0..63
    int v0 = vt << 7, m0 = mt << 6;

    __shared__ float Ash[32 * 68];
    __shared__ float Wsh[32 * 132];
    __shared__ float rmax[1024];
    __shared__ int   rarg[1024];
    __shared__ float smax[64];

    int tid = threadIdx.x;
    int tm = tid >> 4, tn = tid & 15;

    float acc[4][8];
#pragma unroll
    for (int i = 0; i < 4; i++)
#pragma unroll
        for (int j = 0; j < 8; j++) acc[i][j] = 0.0f;

    for (int kc = 0; kc < 4; kc++) {
        int kb = kc << 5;
        __syncthreads();
        {
            int ar = tid >> 2, akq = (tid & 3) << 3;
            const float* ap = g_hid + (size_t)(m0 + ar) * 128 + kb + akq;
            float4 u0 = *(const float4*)ap;
            float4 u1 = *(const float4*)(ap + 4);
            Ash[(akq + 0) * 68 + ar] = u0.x; Ash[(akq + 1) * 68 + ar] = u0.y;
            Ash[(akq + 2) * 68 + ar] = u0.z; Ash[(akq + 3) * 68 + ar] = u0.w;
            Ash[(akq + 4) * 68 + ar] = u1.x; Ash[(akq + 5) * 68 + ar] = u1.y;
            Ash[(akq + 6) * 68 + ar] = u1.z; Ash[(akq + 7) * 68 + ar] = u1.w;

            int wr = tid >> 1, wkq = (tid & 1) << 4;
            const float* wp = w2 + (size_t)(v0 + wr) * 128 + kb + wkq;
            float4 q0 = *(const float4*)wp;
            float4 q1 = *(const float4*)(wp + 4);
            float4 q2 = *(const float4*)(wp + 8);
            float4 q3 = *(const float4*)(wp + 12);
            Wsh[(wkq + 0) * 132 + wr] = q0.x;  Wsh[(wkq + 1) * 132 + wr] = q0.y;
            Wsh[(wkq + 2) * 132 + wr] = q0.z;  Wsh[(wkq + 3) * 132 + wr] = q0.w;
            Wsh[(wkq + 4) * 132 + wr] = q1.x;  Wsh[(wkq + 5) * 132 + wr] = q1.y;
            Wsh[(wkq + 6) * 132 + wr] = q1.z;  Wsh[(wkq + 7) * 132 + wr] = q1.w;
            Wsh[(wkq + 8) * 132 + wr] = q2.x;  Wsh[(wkq + 9) * 132 + wr] = q2.y;
            Wsh[(wkq + 10) * 132 + wr] = q2.z; Wsh[(wkq + 11) * 132 + wr] = q2.w;
            Wsh[(wkq + 12) * 132 + wr] = q3.x; Wsh[(wkq + 13) * 132 + wr] = q3.y;
            Wsh[(wkq + 14) * 132 + wr] = q3.z; Wsh[(wkq + 15) * 132 + wr] = q3.w;
        }
        __syncthreads();
#pragma unroll
        for (int k = 0; k < 32; k++) {
            float4 a = *(const float4*)&Ash[k * 68 + (tm << 2)];
            float4 w0 = *(const float4*)&Wsh[k * 132 + (tn << 3)];
            float4 w1 = *(const float4*)&Wsh[k * 132 + (tn << 3) + 4];
            float av[4] = {a.x, a.y, a.z, a.w};
            float wv[8] = {w0.x, w0.y, w0.z, w0.w, w1.x, w1.y, w1.z, w1.w};
#pragma unroll
            for (int i = 0; i < 4; i++)
#pragma unroll
                for (int j = 0; j < 8; j++) acc[i][j] += av[i] * wv[j];
        }
    }

#pragma unroll
    for (int i = 0; i < 4; i++) {
        int ml = tm * 4 + i;
        float lm = -1e30f;
        int la = 0;
#pragma unroll
        for (int j = 0; j < 8; j++) {
            int v = v0 + (tn << 3) + j;
            float lg = acc[i][j] + b2[v];
            acc[i][j] = lg;
            if (lg > lm) { lm = lg; la = v; }
        }
        rmax[ml * 16 + tn] = lm;
        rarg[ml * 16 + tn] = la;
    }
    __syncthreads();
    if (tid < 64) {
        float bm = -1e30f;
        int ba = 0;
        for (int q = 0; q < 16; q++) {
            float v = rmax[tid * 16 + q];
            if (v > bm) { bm = v; ba = rarg[tid * 16 + q]; }
        }
        smax[tid] = bm;
        g_pmax[(size_t)(m0 + tid) * NVT + vt] = bm;
        g_parg[(size_t)(m0 + tid) * NVT + vt] = ba;
    }
    __syncthreads();
#pragma unroll
    for (int i = 0; i < 4; i++) {
        int ml = tm * 4 + i;
        float s = 0.0f;
        float mx = smax[ml];
#pragma unroll
        for (int j = 0; j < 8; j++) s += __expf(acc[i][j] - mx);
        rmax[ml * 16 + tn] = s;
    }
    __syncthreads();
    if (tid < 64) {
        float s = 0.0f;
        for (int q = 0; q < 16; q++) s += rmax[tid * 16 + q];
        g_psum[(size_t)(m0 + tid) * NVT + vt] = s;
    }
}

// ------------------ per-token combine: lse, argmax, weighted nll ------------------
__global__ __launch_bounds__(256) void k_comb(const float* __restrict__ w2,
                                              const float* __restrict__ b2,
                                              const int* __restrict__ tgt,
                                              const float* __restrict__ cew,
                                              float* __restrict__ dout) {
    int warp = threadIdx.x >> 5, lane = threadIdx.x & 31;
    int m = blockIdx.x * 8 + warp;

    float lm = -1e30f, ls = 0.0f;
    int la = 0;
    for (int vt = lane; vt < NVT; vt += 32) {
        float tmx = g_pmax[(size_t)m * NVT + vt];
        float tsm = g_psum[(size_t)m * NVT + vt];
        int tag = g_parg[(size_t)m * NVT + vt];
        if (tmx > lm) {
            ls = ls * __expf(lm - tmx) + tsm;
            lm = tmx;
            la = tag;
        } else {
            ls += tsm * __expf(tmx - lm);
        }
    }
#pragma unroll
    for (int off = 16; off; off >>= 1) {
        float om = __shfl_down_sync(0xffffffffu, lm, off);
        float os = __shfl_down_sync(0xffffffffu, ls, off);
        int oa = __shfl_down_sync(0xffffffffu, la, off);
        float nm = fmaxf(lm, om);
        float ns = ls * __expf(lm - nm) + os * __expf(om - nm);
        int na = (om > lm) ? oa : ((om == lm && oa < la) ? oa : la);
        lm = nm; ls = ns; la = na;
    }

    int tg = tgt[m];
    float4 hv = *(const float4*)&g_hid[(size_t)m * 128 + lane * 4];
    float4 wv = *(const float4*)&w2[(size_t)tg * 128 + lane * 4];
    float dp = hv.x * wv.x + hv.y * wv.y + hv.z * wv.z + hv.w * wv.w;
#pragma unroll
    for (int off = 16; off; off >>= 1) dp += __shfl_down_sync(0xffffffffu, dp, off);

    if (lane == 0) {
        float logit_t = dp + b2[tg];
        float lse = lm + logf(ls);
        float nll = lse - logit_t;
        float w = cew[tg];
        g_nllw[m] = nll * w;
        g_wtok[m] = w;
        dout[1 + m] = (float)la;
    }
}

// ------------------ final loss reduce ------------------
__global__ __launch_bounds__(256) void k_loss(float* __restrict__ dout) {
    __shared__ float s1[256];
    __shared__ float s2[256];
    int tid = threadIdx.x;
    float a = 0.0f, b = 0.0f;
    for (int i = tid; i < NTOK; i += 256) { a += g_nllw[i]; b += g_wtok[i]; }
    s1[tid] = a; s2[tid] = b;
    __syncthreads();
    for (int off = 128; off; off >>= 1) {
        if (tid < off) { s1[tid] += s1[tid + off]; s2[tid] += s2[tid + off]; }
        __syncthreads();
    }
    if (tid == 0) dout[0] = s1[0] / s2[0];
}

// ------------------ launch ------------------
extern "C" void kernel_launch(void* const* d_in, const int* in_sizes, int n_in,
                              void* d_out, int out_size) {
    const int* inp_word = (const int*)d_in[0];
    const float* inp_mask = (const float*)d_in[1];
    const int* tgt_word = (const int*)d_in[3];
    const float* emb = (const float*)d_in[4];
    const float* w_ih0 = (const float*)d_in[5];
    const float* w_hh0 = (const float*)d_in[6];
    const float* b0 = (const float*)d_in[7];
    const float* w_ih = (const float*)d_in[8];
    const float* w_hh = (const float*)d_in[9];
    const float* bb = (const float*)d_in[10];
    const float* dec_w1 = (const float*)d_in[11];
    const float* dec_b1 = (const float*)d_in[12];
    const float* dec_w2 = (const float*)d_in[13];
    const float* dec_b2 = (const float*)d_in[14];
    const float* cew = (const float*)d_in[15];
    float* out = (float*)d_out;

    float *px0, *pgx, *pA, *pB, *phid;
    cudaGetSymbolAddress((void**)&px0, g_x0);
    cudaGetSymbolAddress((void**)&pgx, g_gx);
    cudaGetSymbolAddress((void**)&pA, g_bufA);
    cudaGetSymbolAddress((void**)&pB, g_bufB);
    cudaGetSymbolAddress((void**)&phid, g_hid);

    const int scan_smem = (32 * 512 + 32 * 516 + 4 * 8 * 32) * 4;
    cudaFuncSetAttribute(k_scan, cudaFuncAttributeMaxDynamicSharedMemorySize, scan_smem);

    // 1. embedding
    k_embed<<<(NTOK * NE) / 256, 256>>>(inp_word, emb);

    // 2. layer 0
    k_gemm<<<dim3(NG / 128, NTOK / 128, 2), 256>>>(px0, w_ih0, b0, pgx,
                                                   NE, NG,
                                                   (long long)NG * NE, NG,
                                                   (long long)NTOK * NG, 0);
    k_zero<<<128, 256>>>();
    k_scan<<<128, 128, scan_smem>>>(pgx, w_hh0, inp_mask, pA);

    // 3. layer 1
    k_gemm<<<dim3(NG / 128, NTOK / 128, 2), 256>>>(pA, w_ih, bb, pgx,
                                                   1024, NG,
                                                   (long long)NG * 1024, NG,
                                                   (long long)NTOK * NG, 0);
    k_zero<<<128, 256>>>();
    k_scan<<<128, 128, scan_smem>>>(pgx, w_hh, inp_mask, pB);

    // 4. layer 2
    k_gemm<<<dim3(NG / 128, NTOK / 128, 2), 256>>>(pB, w_ih + (size_t)2 * NG * 1024,
                                                   bb + 2 * NG, pgx,
                                                   1024, NG,
                                                   (long long)NG * 1024, NG,
                                                   (long long)NTOK * NG, 0);
    k_zero<<<128, 256>>>();
    k_scan<<<128, 128, scan_smem>>>(pgx, w_hh + (size_t)2 * NG * NH, inp_mask, pA);

    // 5. decoder layer 1 (relu)
    k_gemm<<<dim3(1, NTOK / 128, 1), 256>>>(pA, dec_w1, dec_b1, phid,
                                            1024, 128, 0, 0, 0, 1);

    // 6. decoder layer 2 + fused online softmax partials
    k_dec2<<<dim3(NVT, NTOK / 64), 256>>>(dec_w2, dec_b2);

    // 7. per-token combine
    k_comb<<<NTOK / 8, 256>>>(dec_w2, dec_b2, tgt_word, cew, out);

    // 8. loss reduce
    k_loss<<<1, 256>>>(out);
}

// round 5
// speedup vs baseline: 1.1589x; 1.1589x over previous
#include <cuda_runtime.h>
#include <math.h>
#include <stdint.h>

#define NB 32
#define NL 128
#define NH 512
#define NG 2048
#define NV 32000
#define NE 128
#define NTOK 4096
#define NVT 250

// ------------------ scratch ------------------
__device__ float g_x0[NTOK * NE];
__device__ float g_gx[2u * NTOK * NG];          // [dir][m][g], m = b*128+t
__device__ float g_bufA[NTOK * 1024];
__device__ float g_bufB[NTOK * 1024];
__device__ float g_hid[NTOK * 128];
__device__ float g_h[2 * NB * NH];
__device__ float g_c[2 * NB * NH];
__device__ float g_part[2 * 4 * NG * NB];       // [dir][ks][g][b]
__device__ float g_pmax[(size_t)NTOK * NVT];
__device__ float g_psum[(size_t)NTOK * NVT];
__device__ int   g_parg[(size_t)NTOK * NVT];
__device__ float g_nllw[NTOK];
__device__ float g_wtok[NTOK];
__device__ unsigned int g_barcnt;

// ------------------ helpers ------------------
__device__ __forceinline__ float sigf(float x) {
    return 1.0f / (1.0f + __expf(-x));
}
__device__ __forceinline__ float tanhf_fast(float x) {
    float e = __expf(-2.0f * fabsf(x));
    float r = (1.0f - e) / (1.0f + e);
    return copysignf(r, x);
}

__device__ __forceinline__ void gridbar() {
    __syncthreads();
    if (threadIdx.x == 0) {
        __threadfence();
        unsigned int t = atomicAdd(&g_barcnt, 1u);
        unsigned int need = ((t >> 7) + 1u) << 7;
        while (*((volatile unsigned int*)&g_barcnt) < need) {
            __nanosleep(32);
        }
    }
    __syncthreads();
}

// split fp32 into tf32 hi + tf32 lo (bit patterns stored as float)
__device__ __forceinline__ void tf32split(float x, float& hi, float& lo) {
    unsigned hb;
    asm("cvt.rna.tf32.f32 %0, %1;" : "=r"(hb) : "f"(x));
    float hf = __uint_as_float(hb);
    float l = x - hf;
    unsigned lb;
    asm("cvt.rna.tf32.f32 %0, %1;" : "=r"(lb) : "f"(l));
    hi = hf;
    lo = __uint_as_float(lb);
}

#define MMA_TF32(c, a, b)                                                     \
    asm volatile(                                                             \
        "mma.sync.aligned.m16n8k8.row.col.f32.tf32.tf32.f32 "                 \
        "{%0,%1,%2,%3}, {%4,%5,%6,%7}, {%8,%9}, {%0,%1,%2,%3};"               \
        : "+f"((c)[0]), "+f"((c)[1]), "+f"((c)[2]), "+f"((c)[3])              \
        : "r"((a)[0]), "r"((a)[1]), "r"((a)[2]), "r"((a)[3]),                 \
          "r"((b)[0]), "r"((b)[1]))

// ------------------ embedding ------------------
__global__ __launch_bounds__(256) void k_embed(const int* __restrict__ w,
                                               const float* __restrict__ emb) {
    int i = blockIdx.x * 256 + threadIdx.x;
    g_x0[i] = emb[(size_t)w[i >> 7] * NE + (i & 127)];
}

// ------------------ zero h/c + barrier ------------------
__global__ __launch_bounds__(256) void k_zero() {
    int i = blockIdx.x * 256 + threadIdx.x;
    if (i < 2 * NB * NH) { g_h[i] = 0.0f; g_c[i] = 0.0f; }
    if (i == 0) g_barcnt = 0u;
}

// ------------------ 3xTF32 tensor-core GEMM ------------------
// C[m][n] = act(sum_k A[m][k]*W[n][k] + bias[n]); 128x128 tile, BK=16,
// 256 threads = 8 warps (2m x 4n), warp tile 64x32, mma m16n8k8 tf32.
__global__ __launch_bounds__(256) void k_gemm(const float* __restrict__ A,
                                              const float* __restrict__ W,
                                              const float* __restrict__ bias,
                                              float* __restrict__ C,
                                              int K, int N,
                                              long long wStr, long long bStr,
                                              long long cStr, int relu) {
    int d = blockIdx.z;
    W += (size_t)d * wStr;
    bias += (size_t)d * bStr;
    C += (size_t)d * cStr;

    // smem planes, stride 20 floats (80B, 16B aligned; conflict-free frag reads)
    __shared__ float Ah[128 * 20];
    __shared__ float Al[128 * 20];
    __shared__ float Bh[128 * 20];
    __shared__ float Bl[128 * 20];

    int tid = threadIdx.x;
    int m0 = blockIdx.y << 7, n0 = blockIdx.x << 7;

    int lr = tid >> 2;              // 0..63
    int lkq = (tid & 3) << 2;       // 0,4,8,12

    const float* Ap0 = A + (size_t)(m0 + lr) * K + lkq;
    const float* Ap1 = A + (size_t)(m0 + lr + 64) * K + lkq;
    const float* Wp0 = W + (size_t)(n0 + lr) * K + lkq;
    const float* Wp1 = W + (size_t)(n0 + lr + 64) * K + lkq;

    int wid = tid >> 5, lane = tid & 31;
    int gid = lane >> 2, t4 = lane & 3;
    int wm = (wid >> 2) << 6;       // 0 / 64
    int wn = (wid & 3) << 5;        // 0,32,64,96

    float acc[4][4][4];
#pragma unroll
    for (int mt = 0; mt < 4; mt++)
#pragma unroll
        for (int nt = 0; nt < 4; nt++)
#pragma unroll
            for (int r = 0; r < 4; r++) acc[mt][nt][r] = 0.0f;

    for (int kt = 0; kt < K; kt += 16) {
        float4 a0 = *(const float4*)(Ap0 + kt);
        float4 a1 = *(const float4*)(Ap1 + kt);
        float4 w0 = *(const float4*)(Wp0 + kt);
        float4 w1 = *(const float4*)(Wp1 + kt);
        __syncthreads();
        {
            float h, l;
            float* dA0h = &Ah[lr * 20 + lkq];        float* dA0l = &Al[lr * 20 + lkq];
            float* dA1h = &Ah[(lr + 64) * 20 + lkq]; float* dA1l = &Al[(lr + 64) * 20 + lkq];
            float* dB0h = &Bh[lr * 20 + lkq];        float* dB0l = &Bl[lr * 20 + lkq];
            float* dB1h = &Bh[(lr + 64) * 20 + lkq]; float* dB1l = &Bl[(lr + 64) * 20 + lkq];
            tf32split(a0.x, h, l); dA0h[0] = h; dA0l[0] = l;
            tf32split(a0.y, h, l); dA0h[1] = h; dA0l[1] = l;
            tf32split(a0.z, h, l); dA0h[2] = h; dA0l[2] = l;
            tf32split(a0.w, h, l); dA0h[3] = h; dA0l[3] = l;
            tf32split(a1.x, h, l); dA1h[0] = h; dA1l[0] = l;
            tf32split(a1.y, h, l); dA1h[1] = h; dA1l[1] = l;
            tf32split(a1.z, h, l); dA1h[2] = h; dA1l[2] = l;
            tf32split(a1.w, h, l); dA1h[3] = h; dA1l[3] = l;
            tf32split(w0.x, h, l); dB0h[0] = h; dB0l[0] = l;
            tf32split(w0.y, h, l); dB0h[1] = h; dB0l[1] = l;
            tf32split(w0.z, h, l); dB0h[2] = h; dB0l[2] = l;
            tf32split(w0.w, h, l); dB0h[3] = h; dB0l[3] = l;
            tf32split(w1.x, h, l); dB1h[0] = h; dB1l[0] = l;
            tf32split(w1.y, h, l); dB1h[1] = h; dB1l[1] = l;
            tf32split(w1.z, h, l); dB1h[2] = h; dB1l[2] = l;
            tf32split(w1.w, h, l); dB1h[3] = h; dB1l[3] = l;
        }
        __syncthreads();

#pragma unroll
        for (int k8 = 0; k8 < 16; k8 += 8) {
            unsigned ah[4][4], al[4][4];
#pragma unroll
            for (int mt = 0; mt < 4; mt++) {
                int r0i = (wm + (mt << 4) + gid) * 20 + k8 + t4;
                int r1i = (wm + (mt << 4) + gid + 8) * 20 + k8 + t4;
                ah[mt][0] = __float_as_uint(Ah[r0i]);
                ah[mt][1] = __float_as_uint(Ah[r1i]);
                ah[mt][2] = __float_as_uint(Ah[r0i + 4]);
                ah[mt][3] = __float_as_uint(Ah[r1i + 4]);
                al[mt][0] = __float_as_uint(Al[r0i]);
                al[mt][1] = __float_as_uint(Al[r1i]);
                al[mt][2] = __float_as_uint(Al[r0i + 4]);
                al[mt][3] = __float_as_uint(Al[r1i + 4]);
            }
            unsigned bh[4][2], bl[4][2];
#pragma unroll
            for (int nt = 0; nt < 4; nt++) {
                int ci = (wn + (nt << 3) + gid) * 20 + k8 + t4;
                bh[nt][0] = __float_as_uint(Bh[ci]);
                bh[nt][1] = __float_as_uint(Bh[ci + 4]);
                bl[nt][0] = __float_as_uint(Bl[ci]);
                bl[nt][1] = __float_as_uint(Bl[ci + 4]);
            }
#pragma unroll
            for (int mt = 0; mt < 4; mt++)
#pragma unroll
                for (int nt = 0; nt < 4; nt++) {
                    MMA_TF32(acc[mt][nt], ah[mt], bh[nt]);
                    MMA_TF32(acc[mt][nt], ah[mt], bl[nt]);
                    MMA_TF32(acc[mt][nt], al[mt], bh[nt]);
                }
        }
    }

    // epilogue: c0:(gid,2t4) c1:(gid,2t4+1) c2:(gid+8,2t4) c3:(gid+8,2t4+1)
#pragma unroll
    for (int mt = 0; mt < 4; mt++) {
#pragma unroll
        for (int nt = 0; nt < 4; nt++) {
            int m = m0 + wm + (mt << 4) + gid;
            int n = n0 + wn + (nt << 3) + (t4 << 1);
            float bv0 = bias[n], bv1 = bias[n + 1];
            float v0 = acc[mt][nt][0] + bv0;
            float v1 = acc[mt][nt][1] + bv1;
            float v2 = acc[mt][nt][2] + bv0;
            float v3 = acc[mt][nt][3] + bv1;
            if (relu) {
                v0 = fmaxf(v0, 0.0f); v1 = fmaxf(v1, 0.0f);
                v2 = fmaxf(v2, 0.0f); v3 = fmaxf(v3, 0.0f);
            }
            float2 p0 = {v0, v1};
            float2 p1 = {v2, v3};
            *(float2*)(C + (size_t)m * N + n) = p0;
            *(float2*)(C + (size_t)(m + 8) * N + n) = p1;
        }
    }
}

// ------------------ persistent BiLSTM layer scan (v1, proven) ------------------
__global__ __launch_bounds__(128) void k_scan(const float* __restrict__ gx,
                                              const float* __restrict__ whh,
                                              const float* __restrict__ mask,
                                              float* __restrict__ out) {
    __shared__ float Hs[32 * 129];
    __shared__ float Ws[128 * 17];

    int tid = threadIdx.x;
    int bid = blockIdx.x;
    int d = bid >> 6;
    int ks = (bid >> 4) & 3;
    int gt = bid & 15;
    int g0 = gt << 7;
    int k0 = ks << 7;
    const float* whhd = whh + (size_t)d * NG * NH;

    int tg = tid >> 3;
    int tb = tid & 7;

    int jt = bid & 63;
    int jl = tid & 7;
    int bq = tid >> 3;

    for (int s = 0; s < NL; s++) {
        {
            int hb = tid >> 2;
            int hk = (tid & 3) << 5;
            const float* hp = g_h + (size_t)(d * NB + hb) * NH + k0 + hk;
            float* dst = &Hs[hb * 129 + hk];
#pragma unroll
            for (int q = 0; q < 8; q++) {
                float4 v = __ldcg((const float4*)(hp + q * 4));
                dst[q * 4 + 0] = v.x; dst[q * 4 + 1] = v.y;
                dst[q * 4 + 2] = v.z; dst[q * 4 + 3] = v.w;
            }
        }
        float acc[8][4];
#pragma unroll
        for (int i = 0; i < 8; i++)
#pragma unroll
            for (int j = 0; j < 4; j++) acc[i][j] = 0.0f;

        const float* wrow = whhd + (size_t)(g0 + tid) * NH + k0;
        for (int kc = 0; kc < 8; kc++) {
            __syncthreads();
            {
                float4 w0 = *(const float4*)(wrow + kc * 16 + 0);
                float4 w1 = *(const float4*)(wrow + kc * 16 + 4);
                float4 w2 = *(const float4*)(wrow + kc * 16 + 8);
                float4 w3 = *(const float4*)(wrow + kc * 16 + 12);
                float* wd = &Ws[tid * 17];
                wd[0] = w0.x;  wd[1] = w0.y;  wd[2] = w0.z;  wd[3] = w0.w;
                wd[4] = w1.x;  wd[5] = w1.y;  wd[6] = w1.z;  wd[7] = w1.w;
                wd[8] = w2.x;  wd[9] = w2.y;  wd[10] = w2.z; wd[11] = w2.w;
                wd[12] = w3.x; wd[13] = w3.y; wd[14] = w3.z; wd[15] = w3.w;
            }
            __syncthreads();
#pragma unroll
            for (int k = 0; k < 16; k++) {
                float hv[4];
#pragma unroll
                for (int j = 0; j < 4; j++)
                    hv[j] = Hs[(tb * 4 + j) * 129 + (kc << 4) + k];
#pragma unroll
                for (int i = 0; i < 8; i++) {
                    float w = Ws[((tg << 3) + i) * 17 + k];
#pragma unroll
                    for (int j = 0; j < 4; j++) acc[i][j] += w * hv[j];
                }
            }
        }
        {
            size_t pbase = ((size_t)(d * 4 + ks) * NG + g0) * NB;
#pragma unroll
            for (int i = 0; i < 8; i++)
#pragma unroll
                for (int j = 0; j < 4; j++)
                    g_part[pbase + (size_t)((tg << 3) + i) * NB + tb * 4 + j] = acc[i][j];
        }
        __threadfence();
        gridbar();

        int t = d ? (NL - 1 - s) : s;
#pragma unroll
        for (int rep = 0; rep < 2; rep++) {
            int b = bq + (rep << 4);
            int j = (jt << 3) + jl;
            float gate[4];
#pragma unroll
            for (int gi = 0; gi < 4; gi++) {
                int g = gi * NH + j;
                float v = gx[((size_t)d * NTOK + (size_t)b * NL + t) * NG + g];
#pragma unroll
                for (int kss = 0; kss < 4; kss++)
                    v += __ldcg(&g_part[((size_t)(d * 4 + kss) * NG + g) * NB + b]);
                gate[gi] = v;
            }
            float ivg = sigf(gate[0]);
            float fvg = sigf(gate[1]);
            float gvg = tanhf_fast(gate[2]);
            float ovg = sigf(gate[3]);
            size_t hidx = (size_t)(d * NB + b) * NH + j;
            float cold = __ldcg(&g_c[hidx]);
            float cnew = fvg * cold + ivg * gvg;
            float hnew = ovg * tanhf_fast(cnew);
            float mt = mask[b * NL + t];
            float hold = __ldcg(&g_h[hidx]);
            float hh = hold + (hnew - hold) * mt;
            float cc = cold + (cnew - cold) * mt;
            g_c[hidx] = cc;
            g_h[hidx] = hh;
            out[((size_t)b * NL + t) * 1024 + d * NH + j] = hh;
        }
        __threadfence();
        gridbar();
    }
}

// ------------------ decoder2: logits tile + online softmax partials ------------------
__global__ __launch_bounds__(256) void k_dec2(const float* __restrict__ w2,
                                              const float* __restrict__ b2) {
    int vt = blockIdx.x;
    int mt = blockIdx.y;
    int v0 = vt << 7, m0 = mt << 6;

    __shared__ float Ash[32 * 68];
    __shared__ float Wsh[32 * 132];
    __shared__ float rmax[1024];
    __shared__ int   rarg[1024];
    __shared__ float smax[64];

    int tid = threadIdx.x;
    int tm = tid >> 4, tn = tid & 15;

    float acc[4][8];
#pragma unroll
    for (int i = 0; i < 4; i++)
#pragma unroll
        for (int j = 0; j < 8; j++) acc[i][j] = 0.0f;

    for (int kc = 0; kc < 4; kc++) {
        int kb = kc << 5;
        __syncthreads();
        {
            int ar = tid >> 2, akq = (tid & 3) << 3;
            const float* ap = g_hid + (size_t)(m0 + ar) * 128 + kb + akq;
            float4 u0 = *(const float4*)ap;
            float4 u1 = *(const float4*)(ap + 4);
            Ash[(akq + 0) * 68 + ar] = u0.x; Ash[(akq + 1) * 68 + ar] = u0.y;
            Ash[(akq + 2) * 68 + ar] = u0.z; Ash[(akq + 3) * 68 + ar] = u0.w;
            Ash[(akq + 4) * 68 + ar] = u1.x; Ash[(akq + 5) * 68 + ar] = u1.y;
            Ash[(akq + 6) * 68 + ar] = u1.z; Ash[(akq + 7) * 68 + ar] = u1.w;

            int wr = tid >> 1, wkq = (tid & 1) << 4;
            const float* wp = w2 + (size_t)(v0 + wr) * 128 + kb + wkq;
            float4 q0 = *(const float4*)wp;
            float4 q1 = *(const float4*)(wp + 4);
            float4 q2 = *(const float4*)(wp + 8);
            float4 q3 = *(const float4*)(wp + 12);
            Wsh[(wkq + 0) * 132 + wr] = q0.x;  Wsh[(wkq + 1) * 132 + wr] = q0.y;
            Wsh[(wkq + 2) * 132 + wr] = q0.z;  Wsh[(wkq + 3) * 132 + wr] = q0.w;
            Wsh[(wkq + 4) * 132 + wr] = q1.x;  Wsh[(wkq + 5) * 132 + wr] = q1.y;
            Wsh[(wkq + 6) * 132 + wr] = q1.z;  Wsh[(wkq + 7) * 132 + wr] = q1.w;
            Wsh[(wkq + 8) * 132 + wr] = q2.x;  Wsh[(wkq + 9) * 132 + wr] = q2.y;
            Wsh[(wkq + 10) * 132 + wr] = q2.z; Wsh[(wkq + 11) * 132 + wr] = q2.w;
            Wsh[(wkq + 12) * 132 + wr] = q3.x; Wsh[(wkq + 13) * 132 + wr] = q3.y;
            Wsh[(wkq + 14) * 132 + wr] = q3.z; Wsh[(wkq + 15) * 132 + wr] = q3.w;
        }
        __syncthreads();
#pragma unroll
        for (int k = 0; k < 32; k++) {
            float4 a = *(const float4*)&Ash[k * 68 + (tm << 2)];
            float4 w0 = *(const float4*)&Wsh[k * 132 + (tn << 3)];
            float4 w1 = *(const float4*)&Wsh[k * 132 + (tn << 3) + 4];
            float av[4] = {a.x, a.y, a.z, a.w};
            float wv[8] = {w0.x, w0.y, w0.z, w0.w, w1.x, w1.y, w1.z, w1.w};
#pragma unroll
            for (int i = 0; i < 4; i++)
#pragma unroll
                for (int j = 0; j < 8; j++) acc[i][j] += av[i] * wv[j];
        }
    }

#pragma unroll
    for (int i = 0; i < 4; i++) {
        int ml = tm * 4 + i;
        float lm = -1e30f;
        int la = 0;
#pragma unroll
        for (int j = 0; j < 8; j++) {
            int v = v0 + (tn << 3) + j;
            float lg = acc[i][j] + b2[v];
            acc[i][j] = lg;
            if (lg > lm) { lm = lg; la = v; }
        }
        rmax[ml * 16 + tn] = lm;
        rarg[ml * 16 + tn] = la;
    }
    __syncthreads();
    if (tid < 64) {
        float bm = -1e30f;
        int ba = 0;
        for (int q = 0; q < 16; q++) {
            float v = rmax[tid * 16 + q];
            if (v > bm) { bm = v; ba = rarg[tid * 16 + q]; }
        }
        smax[tid] = bm;
        g_pmax[(size_t)(m0 + tid) * NVT + vt] = bm;
        g_parg[(size_t)(m0 + tid) * NVT + vt] = ba;
    }
    __syncthreads();
#pragma unroll
    for (int i = 0; i < 4; i++) {
        int ml = tm * 4 + i;
        float s = 0.0f;
        float mx = smax[ml];
#pragma unroll
        for (int j = 0; j < 8; j++) s += __expf(acc[i][j] - mx);
        rmax[ml * 16 + tn] = s;
    }
    __syncthreads();
    if (tid < 64) {
        float s = 0.0f;
        for (int q = 0; q < 16; q++) s += rmax[tid * 16 + q];
        g_psum[(size_t)(m0 + tid) * NVT + vt] = s;
    }
}

// ------------------ per-token combine ------------------
__global__ __launch_bounds__(256) void k_comb(const float* __restrict__ w2,
                                              const float* __restrict__ b2,
                                              const int* __restrict__ tgt,
                                              const float* __restrict__ cew,
                                              float* __restrict__ dout) {
    int warp = threadIdx.x >> 5, lane = threadIdx.x & 31;
    int m = blockIdx.x * 8 + warp;

    float lm = -1e30f, ls = 0.0f;
    int la = 0;
    for (int vt = lane; vt < NVT; vt += 32) {
        float tmx = g_pmax[(size_t)m * NVT + vt];
        float tsm = g_psum[(size_t)m * NVT + vt];
        int tag = g_parg[(size_t)m * NVT + vt];
        if (tmx > lm) {
            ls = ls * __expf(lm - tmx) + tsm;
            lm = tmx;
            la = tag;
        } else {
            ls += tsm * __expf(tmx - lm);
        }
    }
#pragma unroll
    for (int off = 16; off; off >>= 1) {
        float om = __shfl_down_sync(0xffffffffu, lm, off);
        float os = __shfl_down_sync(0xffffffffu, ls, off);
        int oa = __shfl_down_sync(0xffffffffu, la, off);
        float nm = fmaxf(lm, om);
        float ns = ls * __expf(lm - nm) + os * __expf(om - nm);
        int na = (om > lm) ? oa : ((om == lm && oa < la) ? oa : la);
        lm = nm; ls = ns; la = na;
    }

    int tg = tgt[m];
    float4 hv = *(const float4*)&g_hid[(size_t)m * 128 + lane * 4];
    float4 wv = *(const float4*)&w2[(size_t)tg * 128 + lane * 4];
    float dp = hv.x * wv.x + hv.y * wv.y + hv.z * wv.z + hv.w * wv.w;
#pragma unroll
    for (int off = 16; off; off >>= 1) dp += __shfl_down_sync(0xffffffffu, dp, off);

    if (lane == 0) {
        float logit_t = dp + b2[tg];
        float lse = lm + logf(ls);
        float nll = lse - logit_t;
        float w = cew[tg];
        g_nllw[m] = nll * w;
        g_wtok[m] = w;
        dout[1 + m] = (float)la;
    }
}

// ------------------ final loss reduce ------------------
__global__ __launch_bounds__(256) void k_loss(float* __restrict__ dout) {
    __shared__ float s1[256];
    __shared__ float s2[256];
    int tid = threadIdx.x;
    float a = 0.0f, b = 0.0f;
    for (int i = tid; i < NTOK; i += 256) { a += g_nllw[i]; b += g_wtok[i]; }
    s1[tid] = a; s2[tid] = b;
    __syncthreads();
    for (int off = 128; off; off >>= 1) {
        if (tid < off) { s1[tid] += s1[tid + off]; s2[tid] += s2[tid + off]; }
        __syncthreads();
    }
    if (tid == 0) dout[0] = s1[0] / s2[0];
}

// ------------------ launch ------------------
extern "C" void kernel_launch(void* const* d_in, const int* in_sizes, int n_in,
                              void* d_out, int out_size) {
    const int* inp_word = (const int*)d_in[0];
    const float* inp_mask = (const float*)d_in[1];
    const int* tgt_word = (const int*)d_in[3];
    const float* emb = (const float*)d_in[4];
    const float* w_ih0 = (const float*)d_in[5];
    const float* w_hh0 = (const float*)d_in[6];
    const float* b0 = (const float*)d_in[7];
    const float* w_ih = (const float*)d_in[8];
    const float* w_hh = (const float*)d_in[9];
    const float* bb = (const float*)d_in[10];
    const float* dec_w1 = (const float*)d_in[11];
    const float* dec_b1 = (const float*)d_in[12];
    const float* dec_w2 = (const float*)d_in[13];
    const float* dec_b2 = (const float*)d_in[14];
    const float* cew = (const float*)d_in[15];
    float* out = (float*)d_out;

    float *px0, *pgx, *pA, *pB, *phid;
    cudaGetSymbolAddress((void**)&px0, g_x0);
    cudaGetSymbolAddress((void**)&pgx, g_gx);
    cudaGetSymbolAddress((void**)&pA, g_bufA);
    cudaGetSymbolAddress((void**)&pB, g_bufB);
    cudaGetSymbolAddress((void**)&phid, g_hid);

    // 1. embedding
    k_embed<<<(NTOK * NE) / 256, 256>>>(inp_word, emb);

    // 2. layer 0: gx = x @ Wih0^T + b0 (both dirs)
    k_gemm<<<dim3(NG / 128, NTOK / 128, 2), 256>>>(px0, w_ih0, b0, pgx,
                                                   NE, NG,
                                                   (long long)NG * NE, NG,
                                                   (long long)NTOK * NG, 0);
    k_zero<<<128, 256>>>();
    k_scan<<<128, 128>>>(pgx, w_hh0, inp_mask, pA);

    // 3. layer 1
    k_gemm<<<dim3(NG / 128, NTOK / 128, 2), 256>>>(pA, w_ih, bb, pgx,
                                                   1024, NG,
                                                   (long long)NG * 1024, NG,
                                                   (long long)NTOK * NG, 0);
    k_zero<<<128, 256>>>();
    k_scan<<<128, 128>>>(pgx, w_hh, inp_mask, pB);

    // 4. layer 2
    k_gemm<<<dim3(NG / 128, NTOK / 128, 2), 256>>>(pB, w_ih + (size_t)2 * NG * 1024,
                                                   bb + 2 * NG, pgx,
                                                   1024, NG,
                                                   (long long)NG * 1024, NG,
                                                   (long long)NTOK * NG, 0);
    k_zero<<<128, 256>>>();
    k_scan<<<128, 128>>>(pgx, w_hh + (size_t)2 * NG * NH, inp_mask, pA);

    // 5. decoder layer 1 (relu)
    k_gemm<<<dim3(1, NTOK / 128, 1), 256>>>(pA, dec_w1, dec_b1, phid,
                                            1024, 128, 0, 0, 0, 1);

    // 6. decoder layer 2 + fused online softmax partials
    k_dec2<<<dim3(NVT, NTOK / 64), 256>>>(dec_w2, dec_b2);

    // 7. per-token combine
    k_comb<<<NTOK / 8, 256>>>(dec_w2, dec_b2, tgt_word, cew, out);

    // 8. loss reduce
    k_loss<<<1, 256>>>(out);
}